// round 6
// baseline (speedup 1.0000x reference)
#include <cuda_runtime.h>
#include <math.h>

#define N_NODES 50000
#define D_IN    128
#define D_H     128
#define D_Z     64
#define E_EDGES 800000

#define CHUNK   512
#define NCHUNKS ((N_NODES + CHUNK - 1) / CHUNK)   // 98

typedef unsigned long long ull;

// packed f32x2 helpers (FFMA2 — not emitted by ptxas from C++, PTX only)
__device__ __forceinline__ ull fma2(ull a, ull b, ull c) {
    ull d;
    asm("fma.rn.f32x2 %0, %1, %2, %3;" : "=l"(d) : "l"(a), "l"(b), "l"(c));
    return d;
}
__device__ __forceinline__ ull dup2(float v) {
    ull r;
    asm("mov.b64 %0, {%1, %1};" : "=l"(r) : "f"(v));
    return r;
}
__device__ __forceinline__ void unpack2(ull p, float& lo, float& hi) {
    asm("mov.b64 {%0, %1}, %2;" : "=f"(lo), "=f"(hi) : "l"(p));
}

// ---- scratch (device globals; sanctioned scratch mechanism) ----
__device__ int   g_cnt      [N_NODES];
__device__ int   g_cursor   [N_NODES];
__device__ int   g_row_start[N_NODES + 1];
__device__ int   g_chunk_sum[NCHUNKS];
__device__ int   g_chunk_off[NCHUNKS];
__device__ int   g_csr_src  [E_EDGES];
__device__ float g_dinv     [N_NODES];
__device__ __align__(16) float g_xw [N_NODES * D_H];   // X @ W1
__device__ __align__(16) float g_h  [N_NODES * D_H];   // hidden (post bias+relu)
__device__ __align__(16) float g_agg[N_NODES * D_H];   // A_norm @ hidden

// ---------------------------------------------------------------------------
// CSR build
// ---------------------------------------------------------------------------
__global__ void k_init() {
    int i = blockIdx.x * blockDim.x + threadIdx.x;
    if (i < N_NODES) { g_cnt[i] = 0; g_cursor[i] = 0; }
}

__global__ void k_count(const int* __restrict__ dst) {
    int e = blockIdx.x * blockDim.x + threadIdx.x;
    if (e < E_EDGES) {
        int d = dst[e];
        if ((unsigned)d < N_NODES) atomicAdd(&g_cnt[d], 1);
    }
}

__global__ void k_chunk_sum() {
    __shared__ int sh[CHUNK];
    int t = threadIdx.x;
    int i = blockIdx.x * CHUNK + t;
    int v = (i < N_NODES) ? g_cnt[i] : 0;
    sh[t] = v;
    __syncthreads();
    for (int off = CHUNK / 2; off > 0; off >>= 1) {
        if (t < off) sh[t] += sh[t + off];
        __syncthreads();
    }
    if (t == 0) g_chunk_sum[blockIdx.x] = sh[0];
}

// parallel exclusive scan over the 98 chunk sums (1 block, 128 threads)
__global__ void k_scan_chunks() {
    __shared__ int sh[128];
    int t = threadIdx.x;
    int v = (t < NCHUNKS) ? g_chunk_sum[t] : 0;
    sh[t] = v;
    __syncthreads();
    #pragma unroll
    for (int off = 1; off < 128; off <<= 1) {
        int add = (t >= off) ? sh[t - off] : 0;
        __syncthreads();
        sh[t] += add;
        __syncthreads();
    }
    if (t < NCHUNKS) g_chunk_off[t] = sh[t] - v;   // exclusive
    if (t == 127)    g_row_start[N_NODES] = sh[127];
}

// exclusive scan within each chunk + chunk offset; also dinv = rsqrt(cnt+1)
__global__ void k_chunk_scan() {
    __shared__ int sh[CHUNK];
    int t = threadIdx.x;
    int i = blockIdx.x * CHUNK + t;
    int v = (i < N_NODES) ? g_cnt[i] : 0;
    sh[t] = v;
    __syncthreads();
    for (int off = 1; off < CHUNK; off <<= 1) {
        int add = (t >= off) ? sh[t - off] : 0;
        __syncthreads();
        sh[t] += add;
        __syncthreads();
    }
    if (i < N_NODES) {
        g_row_start[i] = sh[t] - v + g_chunk_off[blockIdx.x];
        g_dinv[i] = rsqrtf((float)(v + 1));     // +1 self-loop
    }
}

__global__ void k_scatter(const int* __restrict__ src,
                          const int* __restrict__ dst) {
    int e = blockIdx.x * blockDim.x + threadIdx.x;
    if (e >= E_EDGES) return;
    int d = dst[e];
    int s = src[e];
    if ((unsigned)d >= N_NODES || (unsigned)s >= N_NODES) return;
    int pos = g_row_start[d] + atomicAdd(&g_cursor[d], 1);
    g_csr_src[pos] = s;
}

// ---------------------------------------------------------------------------
// GEMM1:  g_xw = x @ W1   [N,128]x[128,128]
// 128 threads (t = column), 16 rows/block, row-pairs packed f32x2.
// ---------------------------------------------------------------------------
#define G1_ROWS 16
__global__ void k_gemm1(const float* __restrict__ x,
                        const float* __restrict__ W1) {
    __shared__ __align__(16) float  xs [G1_ROWS][D_IN];        // 8 KB staging
    __shared__ __align__(16) float2 xsp[G1_ROWS / 2][D_IN];    // 8 KB packed
    const int t    = threadIdx.x;
    const int row0 = blockIdx.x * G1_ROWS;

    {
        const float4* src  = (const float4*)(x + (size_t)row0 * D_IN);
        float4*       dstp = (float4*)&xs[0][0];
        #pragma unroll
        for (int i = t; i < G1_ROWS * D_IN / 4; i += 128)
            dstp[i] = src[i];
    }
    __syncthreads();
    #pragma unroll
    for (int m = t; m < (G1_ROWS / 2) * D_IN; m += 128) {
        int rp = m >> 7, k = m & 127;
        xsp[rp][k] = make_float2(xs[2 * rp][k], xs[2 * rp + 1][k]);
    }
    __syncthreads();

    ull acc[G1_ROWS / 2];
    #pragma unroll
    for (int rp = 0; rp < G1_ROWS / 2; ++rp) acc[rp] = 0ull;

    #pragma unroll 4
    for (int k2 = 0; k2 < D_IN / 2; ++k2) {
        const int k = 2 * k2;
        ull w0 = dup2(__ldg(&W1[(k + 0) * D_H + t]));
        ull w1 = dup2(__ldg(&W1[(k + 1) * D_H + t]));
        #pragma unroll
        for (int rp = 0; rp < G1_ROWS / 2; ++rp) {
            ulonglong2 xv = *(const ulonglong2*)&xsp[rp][k];
            acc[rp] = fma2(xv.x, w0, acc[rp]);
            acc[rp] = fma2(xv.y, w1, acc[rp]);
        }
    }

    #pragma unroll
    for (int rp = 0; rp < G1_ROWS / 2; ++rp) {
        float lo, hi;
        unpack2(acc[rp], lo, hi);
        g_xw[(size_t)(row0 + 2 * rp)     * D_H + t] = lo;
        g_xw[(size_t)(row0 + 2 * rp + 1) * D_H + t] = hi;
    }
}

// ---------------------------------------------------------------------------
// gather-aggregate: one warp per dst node, float4 per lane. Edge loop x4.
// LAYER==1: table=g_xw, out=g_h,  epilogue relu(acc + bias)
// LAYER==2: table=g_h,  out=g_agg
// ---------------------------------------------------------------------------
template <int LAYER>
__global__ void k_agg(const float* __restrict__ bias) {
    const float* table = (LAYER == 1) ? g_xw : g_h;
    float*       out   = (LAYER == 1) ? g_h  : g_agg;

    int gtid = blockIdx.x * blockDim.x + threadIdx.x;
    int node = gtid >> 5;
    int lane = gtid & 31;
    if (node >= N_NODES) return;

    const int start = g_row_start[node];
    const int end   = g_row_start[node + 1];
    const float dd  = g_dinv[node];

    // self-loop term
    float4 acc = ((const float4*)(table + (size_t)node * D_H))[lane];
    float sl = dd * dd;
    acc.x *= sl; acc.y *= sl; acc.z *= sl; acc.w *= sl;

    int i = start;
    for (; i + 4 <= end; i += 4) {
        int s0 = g_csr_src[i + 0];
        int s1 = g_csr_src[i + 1];
        int s2 = g_csr_src[i + 2];
        int s3 = g_csr_src[i + 3];
        float n0 = g_dinv[s0] * dd;
        float n1 = g_dinv[s1] * dd;
        float n2 = g_dinv[s2] * dd;
        float n3 = g_dinv[s3] * dd;
        float4 v0 = __ldg(&((const float4*)(table + (size_t)s0 * D_H))[lane]);
        float4 v1 = __ldg(&((const float4*)(table + (size_t)s1 * D_H))[lane]);
        float4 v2 = __ldg(&((const float4*)(table + (size_t)s2 * D_H))[lane]);
        float4 v3 = __ldg(&((const float4*)(table + (size_t)s3 * D_H))[lane]);
        acc.x = fmaf(v0.x, n0, acc.x); acc.y = fmaf(v0.y, n0, acc.y);
        acc.z = fmaf(v0.z, n0, acc.z); acc.w = fmaf(v0.w, n0, acc.w);
        acc.x = fmaf(v1.x, n1, acc.x); acc.y = fmaf(v1.y, n1, acc.y);
        acc.z = fmaf(v1.z, n1, acc.z); acc.w = fmaf(v1.w, n1, acc.w);
        acc.x = fmaf(v2.x, n2, acc.x); acc.y = fmaf(v2.y, n2, acc.y);
        acc.z = fmaf(v2.z, n2, acc.z); acc.w = fmaf(v2.w, n2, acc.w);
        acc.x = fmaf(v3.x, n3, acc.x); acc.y = fmaf(v3.y, n3, acc.y);
        acc.z = fmaf(v3.z, n3, acc.z); acc.w = fmaf(v3.w, n3, acc.w);
    }
    for (; i < end; ++i) {
        int s = g_csr_src[i];
        float norm = g_dinv[s] * dd;
        float4 v = __ldg(&((const float4*)(table + (size_t)s * D_H))[lane]);
        acc.x = fmaf(v.x, norm, acc.x);
        acc.y = fmaf(v.y, norm, acc.y);
        acc.z = fmaf(v.z, norm, acc.z);
        acc.w = fmaf(v.w, norm, acc.w);
    }

    if (LAYER == 1) {
        float4 b = ((const float4*)bias)[lane];
        acc.x = fmaxf(acc.x + b.x, 0.0f);
        acc.y = fmaxf(acc.y + b.y, 0.0f);
        acc.z = fmaxf(acc.z + b.z, 0.0f);
        acc.w = fmaxf(acc.w + b.w, 0.0f);
    }
    ((float4*)(out + (size_t)node * D_H))[lane] = acc;
}

// ---------------------------------------------------------------------------
// GEMM2 + VGAE epilogue (both heads, packed row-pairs):
//   mu = agg@Wmu+bmu ; logstd = agg@Wls+bls ; z = mu + eps*exp(logstd)
// out layout: [z | mu | logstd], each N*64. 64 threads (t=column), 16 rows.
// ---------------------------------------------------------------------------
#define G2_ROWS 16
__global__ void k_gemm2(const float* __restrict__ Wmu,
                        const float* __restrict__ bmu,
                        const float* __restrict__ Wls,
                        const float* __restrict__ bls,
                        const float* __restrict__ eps,
                        float* __restrict__ out) {
    __shared__ __align__(16) float  xs [G2_ROWS][D_H];
    __shared__ __align__(16) float2 xsp[G2_ROWS / 2][D_H];
    const int t    = threadIdx.x;          // 0..63
    const int row0 = blockIdx.x * G2_ROWS;

    {
        const float4* src  = (const float4*)(g_agg + (size_t)row0 * D_H);
        float4*       dstp = (float4*)&xs[0][0];
        #pragma unroll
        for (int i = t; i < G2_ROWS * D_H / 4; i += 64)
            dstp[i] = src[i];
    }
    __syncthreads();
    #pragma unroll
    for (int m = t; m < (G2_ROWS / 2) * D_H; m += 64) {
        int rp = m >> 7, k = m & 127;
        xsp[rp][k] = make_float2(xs[2 * rp][k], xs[2 * rp + 1][k]);
    }
    __syncthreads();

    ull amu[G2_ROWS / 2], als[G2_ROWS / 2];
    #pragma unroll
    for (int rp = 0; rp < G2_ROWS / 2; ++rp) { amu[rp] = 0ull; als[rp] = 0ull; }

    #pragma unroll 4
    for (int k2 = 0; k2 < D_H / 2; ++k2) {
        const int k = 2 * k2;
        ull wm0 = dup2(__ldg(&Wmu[(k + 0) * D_Z + t]));
        ull wm1 = dup2(__ldg(&Wmu[(k + 1) * D_Z + t]));
        ull wl0 = dup2(__ldg(&Wls[(k + 0) * D_Z + t]));
        ull wl1 = dup2(__ldg(&Wls[(k + 1) * D_Z + t]));
        #pragma unroll
        for (int rp = 0; rp < G2_ROWS / 2; ++rp) {
            ulonglong2 xv = *(const ulonglong2*)&xsp[rp][k];
            amu[rp] = fma2(xv.x, wm0, amu[rp]);
            amu[rp] = fma2(xv.y, wm1, amu[rp]);
            als[rp] = fma2(xv.x, wl0, als[rp]);
            als[rp] = fma2(xv.y, wl1, als[rp]);
        }
    }

    const float bm = bmu[t];
    const float bl = bls[t];
    const size_t seg = (size_t)N_NODES * D_Z;

    #pragma unroll
    for (int rp = 0; rp < G2_ROWS / 2; ++rp) {
        float m0, m1, l0, l1;
        unpack2(amu[rp], m0, m1);
        unpack2(als[rp], l0, l1);
        size_t off0 = (size_t)(row0 + 2 * rp)     * D_Z + t;
        size_t off1 = (size_t)(row0 + 2 * rp + 1) * D_Z + t;
        float mu0 = m0 + bm, ls0 = l0 + bl;
        float mu1 = m1 + bm, ls1 = l1 + bl;
        out[off0]           = mu0 + eps[off0] * expf(ls0);
        out[seg + off0]     = mu0;
        out[2 * seg + off0] = ls0;
        out[off1]           = mu1 + eps[off1] * expf(ls1);
        out[seg + off1]     = mu1;
        out[2 * seg + off1] = ls1;
    }
}

// ---------------------------------------------------------------------------
extern "C" void kernel_launch(void* const* d_in, const int* in_sizes, int n_in,
                              void* d_out, int out_size) {
    const float* x   = (const float*)d_in[0];
    const int*   ei  = (const int*)d_in[1];     // [2, E] int32
    const float* eps = (const float*)d_in[2];
    const float* W1  = (const float*)d_in[3];
    const float* b1  = (const float*)d_in[4];
    const float* Wmu = (const float*)d_in[5];
    const float* bmu = (const float*)d_in[6];
    const float* Wls = (const float*)d_in[7];
    const float* bls = (const float*)d_in[8];
    float*       out = (float*)d_out;

    const int* src = ei;            // row 0
    const int* dst = ei + E_EDGES;  // row 1

    // CSR build + degrees
    k_init       <<<(N_NODES + 255) / 256, 256>>>();
    k_count      <<<(E_EDGES + 255) / 256, 256>>>(dst);
    k_chunk_sum  <<<NCHUNKS, CHUNK>>>();
    k_scan_chunks<<<1, 128>>>();
    k_chunk_scan <<<NCHUNKS, CHUNK>>>();
    k_scatter    <<<(E_EDGES + 255) / 256, 256>>>(src, dst);

    // layer 1: dense transform (packed f32x2)
    k_gemm1<<<N_NODES / G1_ROWS, 128>>>(x, W1);

    // aggregations (warp per node)
    {
        long long total = (long long)N_NODES * 32;
        int blocks = (int)((total + 255) / 256);
        k_agg<1><<<blocks, 256>>>(b1);       // g_xw -> g_h (bias+relu)
        k_agg<2><<<blocks, 256>>>(nullptr);  // g_h  -> g_agg
    }

    // output GEMMs + reparameterization (packed f32x2, both heads)
    k_gemm2<<<N_NODES / G2_ROWS, 64>>>(Wmu, bmu, Wls, bls, eps, out);
}

// round 7
// speedup vs baseline: 1.0855x; 1.0855x over previous
#include <cuda_runtime.h>
#include <cuda_fp16.h>
#include <math.h>

#define N_NODES 50000
#define D_IN    128
#define D_H     128
#define D_Z     64
#define E_EDGES 800000

#define CHUNK   512
#define NCHUNKS ((N_NODES + CHUNK - 1) / CHUNK)   // 98

// ---- scratch (device globals; sanctioned scratch mechanism) ----
__device__ int   g_cnt      [N_NODES];
__device__ int   g_cursor   [N_NODES];
__device__ int   g_row_start[N_NODES + 1];
__device__ int   g_chunk_sum[NCHUNKS];
__device__ int   g_chunk_off[NCHUNKS];
__device__ int   g_csr_src  [E_EDGES];
__device__ float g_dinv     [N_NODES];
__device__ __align__(16) __half g_xw[N_NODES * D_H];   // X @ W1        (fp16 gather table)
__device__ __align__(16) __half g_h [N_NODES * D_H];   // hidden        (fp16 gather table)
__device__ __align__(16) float  g_agg[N_NODES * D_H];  // A_norm @ hidden (fp32, feeds gemm2)

// ---------------------------------------------------------------------------
// CSR build
// ---------------------------------------------------------------------------
__global__ void k_init() {
    int i = blockIdx.x * blockDim.x + threadIdx.x;
    if (i < N_NODES) { g_cnt[i] = 0; g_cursor[i] = 0; }
}

__global__ void k_count(const int* __restrict__ dst) {
    int e = blockIdx.x * blockDim.x + threadIdx.x;
    if (e < E_EDGES) {
        int d = dst[e];
        if ((unsigned)d < N_NODES) atomicAdd(&g_cnt[d], 1);
    }
}

__global__ void k_chunk_sum() {
    __shared__ int sh[CHUNK];
    int t = threadIdx.x;
    int i = blockIdx.x * CHUNK + t;
    int v = (i < N_NODES) ? g_cnt[i] : 0;
    sh[t] = v;
    __syncthreads();
    for (int off = CHUNK / 2; off > 0; off >>= 1) {
        if (t < off) sh[t] += sh[t + off];
        __syncthreads();
    }
    if (t == 0) g_chunk_sum[blockIdx.x] = sh[0];
}

// parallel exclusive scan over the 98 chunk sums (1 block, 128 threads)
__global__ void k_scan_chunks() {
    __shared__ int sh[128];
    int t = threadIdx.x;
    int v = (t < NCHUNKS) ? g_chunk_sum[t] : 0;
    sh[t] = v;
    __syncthreads();
    #pragma unroll
    for (int off = 1; off < 128; off <<= 1) {
        int add = (t >= off) ? sh[t - off] : 0;
        __syncthreads();
        sh[t] += add;
        __syncthreads();
    }
    if (t < NCHUNKS) g_chunk_off[t] = sh[t] - v;   // exclusive
    if (t == 127)    g_row_start[N_NODES] = sh[127];
}

// exclusive scan within each chunk + chunk offset; also dinv = rsqrt(cnt+1)
__global__ void k_chunk_scan() {
    __shared__ int sh[CHUNK];
    int t = threadIdx.x;
    int i = blockIdx.x * CHUNK + t;
    int v = (i < N_NODES) ? g_cnt[i] : 0;
    sh[t] = v;
    __syncthreads();
    for (int off = 1; off < CHUNK; off <<= 1) {
        int add = (t >= off) ? sh[t - off] : 0;
        __syncthreads();
        sh[t] += add;
        __syncthreads();
    }
    if (i < N_NODES) {
        g_row_start[i] = sh[t] - v + g_chunk_off[blockIdx.x];
        g_dinv[i] = rsqrtf((float)(v + 1));     // +1 self-loop
    }
}

__global__ void k_scatter(const int* __restrict__ src,
                          const int* __restrict__ dst) {
    int e = blockIdx.x * blockDim.x + threadIdx.x;
    if (e >= E_EDGES) return;
    int d = dst[e];
    int s = src[e];
    if ((unsigned)d >= N_NODES || (unsigned)s >= N_NODES) return;
    int pos = g_row_start[d] + atomicAdd(&g_cursor[d], 1);
    g_csr_src[pos] = s;
}

// ---------------------------------------------------------------------------
// GEMM1:  g_xw = fp16(x @ W1)   [N,128]x[128,128]
// 128 threads, 8 rows/block; thread t owns column t. (R5 mainloop)
// ---------------------------------------------------------------------------
#define G1_ROWS 8
__global__ void k_gemm1(const float* __restrict__ x,
                        const float* __restrict__ W1) {
    __shared__ __align__(16) float xs[G1_ROWS][D_IN];
    const int t    = threadIdx.x;
    const int row0 = blockIdx.x * G1_ROWS;

    {
        const float4* src  = (const float4*)(x + (size_t)row0 * D_IN);
        float4*       dstp = (float4*)&xs[0][0];
        #pragma unroll
        for (int i = t; i < G1_ROWS * D_IN / 4; i += 128)
            dstp[i] = src[i];
    }
    __syncthreads();

    float acc[G1_ROWS];
    #pragma unroll
    for (int r = 0; r < G1_ROWS; ++r) acc[r] = 0.0f;

    #pragma unroll 8
    for (int k4 = 0; k4 < D_IN / 4; ++k4) {
        const int k = k4 * 4;
        float w0 = __ldg(&W1[(k + 0) * D_H + t]);
        float w1 = __ldg(&W1[(k + 1) * D_H + t]);
        float w2 = __ldg(&W1[(k + 2) * D_H + t]);
        float w3 = __ldg(&W1[(k + 3) * D_H + t]);
        #pragma unroll
        for (int r = 0; r < G1_ROWS; ++r) {
            float4 xv = *(const float4*)&xs[r][k];
            acc[r] = fmaf(xv.x, w0, acc[r]);
            acc[r] = fmaf(xv.y, w1, acc[r]);
            acc[r] = fmaf(xv.z, w2, acc[r]);
            acc[r] = fmaf(xv.w, w3, acc[r]);
        }
    }

    #pragma unroll
    for (int r = 0; r < G1_ROWS; ++r)
        g_xw[(size_t)(row0 + r) * D_H + t] = __float2half(acc[r]);
}

// ---------------------------------------------------------------------------
// gather-aggregate over fp16 tables, fp32 accumulation.
// one warp per dst node; each lane owns 4 consecutive columns (uint2 = 4 halves).
// LAYER==1: table=g_xw -> g_h (fp16), epilogue relu(acc + bias)
// LAYER==2: table=g_h  -> g_agg (fp32)
// ---------------------------------------------------------------------------
__device__ __forceinline__ void h4_fma(float4& acc, uint2 u, float n) {
    __half2 a = *reinterpret_cast<__half2*>(&u.x);
    __half2 b = *reinterpret_cast<__half2*>(&u.y);
    float2 fa = __half22float2(a);
    float2 fb = __half22float2(b);
    acc.x = fmaf(fa.x, n, acc.x);
    acc.y = fmaf(fa.y, n, acc.y);
    acc.z = fmaf(fb.x, n, acc.z);
    acc.w = fmaf(fb.y, n, acc.w);
}

template <int LAYER>
__global__ void k_agg(const float* __restrict__ bias) {
    const __half* table = (LAYER == 1) ? g_xw : g_h;

    int gtid = blockIdx.x * blockDim.x + threadIdx.x;
    int node = gtid >> 5;
    int lane = gtid & 31;
    if (node >= N_NODES) return;

    const int start = g_row_start[node];
    const int end   = g_row_start[node + 1];
    const float dd  = g_dinv[node];

    // self-loop term
    float4 acc = make_float4(0.f, 0.f, 0.f, 0.f);
    {
        uint2 u = __ldg((const uint2*)(table + (size_t)node * D_H) + lane);
        h4_fma(acc, u, dd * dd);
    }

    int i = start;
    for (; i + 4 <= end; i += 4) {
        int s0 = g_csr_src[i + 0];
        int s1 = g_csr_src[i + 1];
        int s2 = g_csr_src[i + 2];
        int s3 = g_csr_src[i + 3];
        float n0 = g_dinv[s0] * dd;
        float n1 = g_dinv[s1] * dd;
        float n2 = g_dinv[s2] * dd;
        float n3 = g_dinv[s3] * dd;
        uint2 u0 = __ldg((const uint2*)(table + (size_t)s0 * D_H) + lane);
        uint2 u1 = __ldg((const uint2*)(table + (size_t)s1 * D_H) + lane);
        uint2 u2 = __ldg((const uint2*)(table + (size_t)s2 * D_H) + lane);
        uint2 u3 = __ldg((const uint2*)(table + (size_t)s3 * D_H) + lane);
        h4_fma(acc, u0, n0);
        h4_fma(acc, u1, n1);
        h4_fma(acc, u2, n2);
        h4_fma(acc, u3, n3);
    }
    for (; i < end; ++i) {
        int s = g_csr_src[i];
        float norm = g_dinv[s] * dd;
        uint2 u = __ldg((const uint2*)(table + (size_t)s * D_H) + lane);
        h4_fma(acc, u, norm);
    }

    if (LAYER == 1) {
        float4 b = ((const float4*)bias)[lane];
        acc.x = fmaxf(acc.x + b.x, 0.0f);
        acc.y = fmaxf(acc.y + b.y, 0.0f);
        acc.z = fmaxf(acc.z + b.z, 0.0f);
        acc.w = fmaxf(acc.w + b.w, 0.0f);
        // store hidden as fp16 gather table
        uint2 o;
        __half2 h0 = __floats2half2_rn(acc.x, acc.y);
        __half2 h1 = __floats2half2_rn(acc.z, acc.w);
        o.x = *reinterpret_cast<unsigned*>(&h0);
        o.y = *reinterpret_cast<unsigned*>(&h1);
        ((uint2*)(g_h + (size_t)node * D_H))[lane] = o;
    } else {
        ((float4*)(g_agg + (size_t)node * D_H))[lane] = acc;
    }
}

// ---------------------------------------------------------------------------
// GEMM2 + VGAE epilogue (R5 form):
//   mu = agg@Wmu+bmu ; logstd = agg@Wls+bls ; z = mu + eps*exp(logstd)
// out layout: [z | mu | logstd], each N*64
// ---------------------------------------------------------------------------
#define G2_ROWS 8
__global__ void k_gemm2(const float* __restrict__ Wmu,
                        const float* __restrict__ bmu,
                        const float* __restrict__ Wls,
                        const float* __restrict__ bls,
                        const float* __restrict__ eps,
                        float* __restrict__ out) {
    __shared__ __align__(16) float xs[G2_ROWS][D_H];
    const int t    = threadIdx.x;          // 0..63
    const int row0 = blockIdx.x * G2_ROWS;

    {
        const float4* src  = (const float4*)(g_agg + (size_t)row0 * D_H);
        float4*       dstp = (float4*)&xs[0][0];
        #pragma unroll
        for (int i = t; i < G2_ROWS * D_H / 4; i += 64)
            dstp[i] = src[i];
    }
    __syncthreads();

    float amu[G2_ROWS], als[G2_ROWS];
    #pragma unroll
    for (int r = 0; r < G2_ROWS; ++r) { amu[r] = 0.0f; als[r] = 0.0f; }

    #pragma unroll 8
    for (int k4 = 0; k4 < D_H / 4; ++k4) {
        const int k = k4 * 4;
        float wm0 = __ldg(&Wmu[(k + 0) * D_Z + t]);
        float wm1 = __ldg(&Wmu[(k + 1) * D_Z + t]);
        float wm2 = __ldg(&Wmu[(k + 2) * D_Z + t]);
        float wm3 = __ldg(&Wmu[(k + 3) * D_Z + t]);
        float wl0 = __ldg(&Wls[(k + 0) * D_Z + t]);
        float wl1 = __ldg(&Wls[(k + 1) * D_Z + t]);
        float wl2 = __ldg(&Wls[(k + 2) * D_Z + t]);
        float wl3 = __ldg(&Wls[(k + 3) * D_Z + t]);
        #pragma unroll
        for (int r = 0; r < G2_ROWS; ++r) {
            float4 xv = *(const float4*)&xs[r][k];
            amu[r] = fmaf(xv.x, wm0, amu[r]);
            amu[r] = fmaf(xv.y, wm1, amu[r]);
            amu[r] = fmaf(xv.z, wm2, amu[r]);
            amu[r] = fmaf(xv.w, wm3, amu[r]);
            als[r] = fmaf(xv.x, wl0, als[r]);
            als[r] = fmaf(xv.y, wl1, als[r]);
            als[r] = fmaf(xv.z, wl2, als[r]);
            als[r] = fmaf(xv.w, wl3, als[r]);
        }
    }

    const float bm = bmu[t];
    const float bl = bls[t];
    const size_t seg = (size_t)N_NODES * D_Z;

    #pragma unroll
    for (int r = 0; r < G2_ROWS; ++r) {
        size_t off = (size_t)(row0 + r) * D_Z + t;
        float mu = amu[r] + bm;
        float ls = als[r] + bl;
        float z  = mu + eps[off] * expf(ls);
        out[off]           = z;
        out[seg + off]     = mu;
        out[2 * seg + off] = ls;
    }
}

// ---------------------------------------------------------------------------
extern "C" void kernel_launch(void* const* d_in, const int* in_sizes, int n_in,
                              void* d_out, int out_size) {
    const float* x   = (const float*)d_in[0];
    const int*   ei  = (const int*)d_in[1];     // [2, E] int32
    const float* eps = (const float*)d_in[2];
    const float* W1  = (const float*)d_in[3];
    const float* b1  = (const float*)d_in[4];
    const float* Wmu = (const float*)d_in[5];
    const float* bmu = (const float*)d_in[6];
    const float* Wls = (const float*)d_in[7];
    const float* bls = (const float*)d_in[8];
    float*       out = (float*)d_out;

    const int* src = ei;            // row 0
    const int* dst = ei + E_EDGES;  // row 1

    // CSR build + degrees
    k_init       <<<(N_NODES + 255) / 256, 256>>>();
    k_count      <<<(E_EDGES + 255) / 256, 256>>>(dst);
    k_chunk_sum  <<<NCHUNKS, CHUNK>>>();
    k_scan_chunks<<<1, 128>>>();
    k_chunk_scan <<<NCHUNKS, CHUNK>>>();
    k_scatter    <<<(E_EDGES + 255) / 256, 256>>>(src, dst);

    // layer 1: dense transform -> fp16 table
    k_gemm1<<<N_NODES / G1_ROWS, 128>>>(x, W1);

    // aggregations (warp per node, fp16 gather / fp32 accumulate)
    {
        long long total = (long long)N_NODES * 32;
        int blocks = (int)((total + 255) / 256);
        k_agg<1><<<blocks, 256>>>(b1);       // g_xw -> g_h (bias+relu, fp16)
        k_agg<2><<<blocks, 256>>>(nullptr);  // g_h  -> g_agg (fp32)
    }

    // output GEMMs + reparameterization
    k_gemm2<<<N_NODES / G2_ROWS, 64>>>(Wmu, bmu, Wls, bls, eps, out);
}

// round 8
// speedup vs baseline: 1.1454x; 1.0552x over previous
#include <cuda_runtime.h>
#include <cuda_fp16.h>
#include <mma.h>
#include <math.h>

using namespace nvcuda;

#define N_NODES 50000
#define N_PAD   50048              // 782 * 64
#define D_IN    128
#define D_H     128
#define D_Z     64
#define E_EDGES 800000

#define CHUNK   512
#define NCHUNKS ((N_NODES + CHUNK - 1) / CHUNK)   // 98

// ---- scratch (device globals; sanctioned scratch mechanism) ----
__device__ int   g_cnt      [N_NODES];
__device__ int   g_cursor   [N_NODES];
__device__ int   g_row_start[N_NODES + 1];
__device__ int   g_chunk_sum[NCHUNKS];
__device__ int   g_chunk_off[NCHUNKS];
__device__ int   g_csr_src  [E_EDGES];
__device__ float g_dinv     [N_NODES];
__device__ __align__(16) __half g_w1h [D_IN * D_H];     // fp16 W1
__device__ __align__(16) __half g_w2h [D_H * 128];      // fp16 [Wmu | Wls]
__device__ __align__(16) __half g_xw  [N_NODES * D_H];  // (X@W1) * dinv[row]  (pre-scaled)
__device__ __align__(16) __half g_h   [N_NODES * D_H];  // hidden * dinv[row]  (pre-scaled)
__device__ __align__(16) __half g_aggh[(size_t)N_PAD * D_H]; // A_norm@hidden (fp16; padded rows stay 0)

// ---------------------------------------------------------------------------
// CSR build
// ---------------------------------------------------------------------------
__global__ void k_init() {
    int i = blockIdx.x * blockDim.x + threadIdx.x;
    if (i < N_NODES) { g_cnt[i] = 0; g_cursor[i] = 0; }
}

__global__ void k_count(const int* __restrict__ dst) {
    int e = blockIdx.x * blockDim.x + threadIdx.x;
    if (e < E_EDGES) {
        int d = dst[e];
        if ((unsigned)d < N_NODES) atomicAdd(&g_cnt[d], 1);
    }
}

__global__ void k_chunk_sum() {
    __shared__ int sh[CHUNK];
    int t = threadIdx.x;
    int i = blockIdx.x * CHUNK + t;
    int v = (i < N_NODES) ? g_cnt[i] : 0;
    sh[t] = v;
    __syncthreads();
    for (int off = CHUNK / 2; off > 0; off >>= 1) {
        if (t < off) sh[t] += sh[t + off];
        __syncthreads();
    }
    if (t == 0) g_chunk_sum[blockIdx.x] = sh[0];
}

__global__ void k_scan_chunks() {
    __shared__ int sh[128];
    int t = threadIdx.x;
    int v = (t < NCHUNKS) ? g_chunk_sum[t] : 0;
    sh[t] = v;
    __syncthreads();
    #pragma unroll
    for (int off = 1; off < 128; off <<= 1) {
        int add = (t >= off) ? sh[t - off] : 0;
        __syncthreads();
        sh[t] += add;
        __syncthreads();
    }
    if (t < NCHUNKS) g_chunk_off[t] = sh[t] - v;
    if (t == 127)    g_row_start[N_NODES] = sh[127];
}

__global__ void k_chunk_scan() {
    __shared__ int sh[CHUNK];
    int t = threadIdx.x;
    int i = blockIdx.x * CHUNK + t;
    int v = (i < N_NODES) ? g_cnt[i] : 0;
    sh[t] = v;
    __syncthreads();
    for (int off = 1; off < CHUNK; off <<= 1) {
        int add = (t >= off) ? sh[t - off] : 0;
        __syncthreads();
        sh[t] += add;
        __syncthreads();
    }
    if (i < N_NODES) {
        g_row_start[i] = sh[t] - v + g_chunk_off[blockIdx.x];
        g_dinv[i] = rsqrtf((float)(v + 1));     // +1 self-loop
    }
}

__global__ void k_scatter(const int* __restrict__ src,
                          const int* __restrict__ dst) {
    int e = blockIdx.x * blockDim.x + threadIdx.x;
    if (e >= E_EDGES) return;
    int d = dst[e];
    int s = src[e];
    if ((unsigned)d >= N_NODES || (unsigned)s >= N_NODES) return;
    int pos = g_row_start[d] + atomicAdd(&g_cursor[d], 1);
    g_csr_src[pos] = s;
}

// ---------------------------------------------------------------------------
// weight conversion: W1 -> g_w1h ; [Wmu|Wls] -> g_w2h
// ---------------------------------------------------------------------------
__global__ void k_cvt_w(const float* __restrict__ W1,
                        const float* __restrict__ Wmu,
                        const float* __restrict__ Wls) {
    int i = blockIdx.x * blockDim.x + threadIdx.x;  // 0..32767
    if (i < D_IN * D_H) {
        g_w1h[i] = __float2half(W1[i]);
    } else {
        int j = i - D_IN * D_H;
        int k = j >> 7, n = j & 127;
        float v = (n < 64) ? Wmu[k * 64 + n] : Wls[k * 64 + (n - 64)];
        g_w2h[j] = __float2half(v);
    }
}

// ---------------------------------------------------------------------------
// GEMM1 (tensor cores): g_xw = fp16( (x @ W1) * dinv[row] )
// 256 threads = 8 warps (4 row-tiles x 2 col-tiles), 64 rows/block.
// ---------------------------------------------------------------------------
__global__ void k_gemm1(const float* __restrict__ x) {
    __shared__ __align__(16) char smraw[49152];
    __half* Ah = (__half*)smraw;              // 64x128 fp16 = 16 KB
    __half* Bh = (__half*)(smraw + 16384);    // 128x128 fp16 = 32 KB
    float*  Cs = (float*)smraw;               // 64x128 f32 = 32 KB (overlays A/B after mainloop)

    const int tid  = threadIdx.x;
    const int row0 = blockIdx.x * 64;

    // stage A: convert f32 -> f16 (zero-pad OOB rows)
    for (int i = tid; i < 64 * 32; i += 256) {
        int r = i >> 5, c4 = i & 31;
        int rg = row0 + r;
        float4 v = make_float4(0.f, 0.f, 0.f, 0.f);
        if (rg < N_NODES) v = ((const float4*)(x + (size_t)rg * D_IN))[c4];
        __half2 h0 = __floats2half2_rn(v.x, v.y);
        __half2 h1 = __floats2half2_rn(v.z, v.w);
        uint2 u;
        u.x = *reinterpret_cast<unsigned*>(&h0);
        u.y = *reinterpret_cast<unsigned*>(&h1);
        ((uint2*)Ah)[i] = u;
    }
    // stage B
    for (int i = tid; i < 2048; i += 256)
        ((uint4*)Bh)[i] = ((const uint4*)g_w1h)[i];
    __syncthreads();

    const int wid = tid >> 5, wr = wid & 3, wc = wid >> 2;

    wmma::fragment<wmma::accumulator, 16, 16, 16, float> fc[4];
    #pragma unroll
    for (int c = 0; c < 4; ++c) wmma::fill_fragment(fc[c], 0.0f);

    #pragma unroll
    for (int k = 0; k < 8; ++k) {
        wmma::fragment<wmma::matrix_a, 16, 16, 16, __half, wmma::row_major> fa;
        wmma::load_matrix_sync(fa, Ah + (wr * 16) * 128 + k * 16, 128);
        #pragma unroll
        for (int c = 0; c < 4; ++c) {
            wmma::fragment<wmma::matrix_b, 16, 16, 16, __half, wmma::row_major> fb;
            wmma::load_matrix_sync(fb, Bh + (k * 16) * 128 + wc * 64 + c * 16, 128);
            wmma::mma_sync(fc[c], fa, fb, fc[c]);
        }
    }
    __syncthreads();   // all MMA reads done before C overlays A/B

    #pragma unroll
    for (int c = 0; c < 4; ++c)
        wmma::store_matrix_sync(Cs + (wr * 16) * 128 + wc * 64 + c * 16, fc[c],
                                128, wmma::mem_row_major);
    __syncthreads();

    // epilogue: scale by dinv[row], convert to fp16
    for (int i = tid; i < 64 * 32; i += 256) {
        int r = i >> 5, c4 = i & 31;
        int rg = row0 + r;
        if (rg >= N_NODES) continue;
        float di = g_dinv[rg];
        float4 v = ((const float4*)(Cs + r * 128))[c4];
        __half2 h0 = __floats2half2_rn(v.x * di, v.y * di);
        __half2 h1 = __floats2half2_rn(v.z * di, v.w * di);
        uint2 u;
        u.x = *reinterpret_cast<unsigned*>(&h0);
        u.y = *reinterpret_cast<unsigned*>(&h1);
        ((uint2*)(g_xw + (size_t)rg * D_H))[c4] = u;
    }
}

// ---------------------------------------------------------------------------
// gather-aggregate over PRE-SCALED fp16 tables, fp32 accumulation.
// acc = table[node] + sum_s table[s];   result = acc * dinv[node]
// LAYER==1: h = relu(result + b); store fp16(h * dinv[node]) -> g_h
// LAYER==2: store fp16(result) -> g_aggh
// ---------------------------------------------------------------------------
__device__ __forceinline__ void h4_add(float4& acc, uint2 u) {
    __half2 a = *reinterpret_cast<__half2*>(&u.x);
    __half2 b = *reinterpret_cast<__half2*>(&u.y);
    float2 fa = __half22float2(a);
    float2 fb = __half22float2(b);
    acc.x += fa.x; acc.y += fa.y; acc.z += fb.x; acc.w += fb.y;
}

template <int LAYER>
__global__ void k_agg(const float* __restrict__ bias) {
    const __half* table = (LAYER == 1) ? g_xw : g_h;

    int gtid = blockIdx.x * blockDim.x + threadIdx.x;
    int node = gtid >> 5;
    int lane = gtid & 31;
    if (node >= N_NODES) return;

    const int start = g_row_start[node];
    const int end   = g_row_start[node + 1];
    const float dd  = g_dinv[node];

    float4 acc = make_float4(0.f, 0.f, 0.f, 0.f);
    h4_add(acc, __ldg((const uint2*)(table + (size_t)node * D_H) + lane));  // self

    int i = start;
    for (; i + 4 <= end; i += 4) {
        int s0 = g_csr_src[i + 0];
        int s1 = g_csr_src[i + 1];
        int s2 = g_csr_src[i + 2];
        int s3 = g_csr_src[i + 3];
        uint2 u0 = __ldg((const uint2*)(table + (size_t)s0 * D_H) + lane);
        uint2 u1 = __ldg((const uint2*)(table + (size_t)s1 * D_H) + lane);
        uint2 u2 = __ldg((const uint2*)(table + (size_t)s2 * D_H) + lane);
        uint2 u3 = __ldg((const uint2*)(table + (size_t)s3 * D_H) + lane);
        h4_add(acc, u0);
        h4_add(acc, u1);
        h4_add(acc, u2);
        h4_add(acc, u3);
    }
    for (; i < end; ++i) {
        int s = g_csr_src[i];
        h4_add(acc, __ldg((const uint2*)(table + (size_t)s * D_H) + lane));
    }

    acc.x *= dd; acc.y *= dd; acc.z *= dd; acc.w *= dd;

    uint2 o;
    if (LAYER == 1) {
        float4 b = ((const float4*)bias)[lane];
        float hx = fmaxf(acc.x + b.x, 0.0f) * dd;
        float hy = fmaxf(acc.y + b.y, 0.0f) * dd;
        float hz = fmaxf(acc.z + b.z, 0.0f) * dd;
        float hw = fmaxf(acc.w + b.w, 0.0f) * dd;
        __half2 h0 = __floats2half2_rn(hx, hy);
        __half2 h1 = __floats2half2_rn(hz, hw);
        o.x = *reinterpret_cast<unsigned*>(&h0);
        o.y = *reinterpret_cast<unsigned*>(&h1);
        ((uint2*)(g_h + (size_t)node * D_H))[lane] = o;
    } else {
        __half2 h0 = __floats2half2_rn(acc.x, acc.y);
        __half2 h1 = __floats2half2_rn(acc.z, acc.w);
        o.x = *reinterpret_cast<unsigned*>(&h0);
        o.y = *reinterpret_cast<unsigned*>(&h1);
        ((uint2*)(g_aggh + (size_t)node * D_H))[lane] = o;
    }
}

// ---------------------------------------------------------------------------
// GEMM2 (tensor cores) + VGAE epilogue:
//   [mu | ls] = g_aggh @ [Wmu|Wls] ; z = mu+bmu + eps*exp(ls+bls)
// A frags loaded straight from global fp16 (padded rows are zero).
// ---------------------------------------------------------------------------
__global__ void k_gemm2(const float* __restrict__ bmu,
                        const float* __restrict__ bls,
                        const float* __restrict__ eps,
                        float* __restrict__ out) {
    __shared__ __align__(16) char smraw[32768];
    __half* Bh = (__half*)smraw;             // 128x128 fp16 = 32 KB
    float*  Cs = (float*)smraw;              // 64x128 f32 = 32 KB (overlays B)

    const int tid  = threadIdx.x;
    const int row0 = blockIdx.x * 64;

    for (int i = tid; i < 2048; i += 256)
        ((uint4*)Bh)[i] = ((const uint4*)g_w2h)[i];
    __syncthreads();

    const int wid = tid >> 5, wr = wid & 3, wc = wid >> 2;
    const __half* Ag = g_aggh + (size_t)(row0 + wr * 16) * D_H;

    wmma::fragment<wmma::accumulator, 16, 16, 16, float> fc[4];
    #pragma unroll
    for (int c = 0; c < 4; ++c) wmma::fill_fragment(fc[c], 0.0f);

    #pragma unroll
    for (int k = 0; k < 8; ++k) {
        wmma::fragment<wmma::matrix_a, 16, 16, 16, __half, wmma::row_major> fa;
        wmma::load_matrix_sync(fa, Ag + k * 16, 128);
        #pragma unroll
        for (int c = 0; c < 4; ++c) {
            wmma::fragment<wmma::matrix_b, 16, 16, 16, __half, wmma::row_major> fb;
            wmma::load_matrix_sync(fb, Bh + (k * 16) * 128 + wc * 64 + c * 16, 128);
            wmma::mma_sync(fc[c], fa, fb, fc[c]);
        }
    }
    __syncthreads();

    #pragma unroll
    for (int c = 0; c < 4; ++c)
        wmma::store_matrix_sync(Cs + (wr * 16) * 128 + wc * 64 + c * 16, fc[c],
                                128, wmma::mem_row_major);
    __syncthreads();

    const size_t seg = (size_t)N_NODES * D_Z;
    for (int i = tid; i < 64 * 64; i += 256) {
        int r = i >> 6, c = i & 63;
        int rg = row0 + r;
        if (rg >= N_NODES) continue;
        float mu = Cs[r * 128 + c]      + bmu[c];
        float ls = Cs[r * 128 + 64 + c] + bls[c];
        size_t off = (size_t)rg * D_Z + c;
        out[off]           = mu + eps[off] * expf(ls);
        out[seg + off]     = mu;
        out[2 * seg + off] = ls;
    }
}

// ---------------------------------------------------------------------------
extern "C" void kernel_launch(void* const* d_in, const int* in_sizes, int n_in,
                              void* d_out, int out_size) {
    const float* x   = (const float*)d_in[0];
    const int*   ei  = (const int*)d_in[1];     // [2, E] int32
    const float* eps = (const float*)d_in[2];
    const float* W1  = (const float*)d_in[3];
    const float* b1  = (const float*)d_in[4];
    const float* Wmu = (const float*)d_in[5];
    const float* bmu = (const float*)d_in[6];
    const float* Wls = (const float*)d_in[7];
    const float* bls = (const float*)d_in[8];
    float*       out = (float*)d_out;

    const int* src = ei;
    const int* dst = ei + E_EDGES;

    // CSR build + degrees
    k_init       <<<(N_NODES + 255) / 256, 256>>>();
    k_count      <<<(E_EDGES + 255) / 256, 256>>>(dst);
    k_chunk_sum  <<<NCHUNKS, CHUNK>>>();
    k_scan_chunks<<<1, 128>>>();
    k_chunk_scan <<<NCHUNKS, CHUNK>>>();
    k_scatter    <<<(E_EDGES + 255) / 256, 256>>>(src, dst);

    // weight fp16 conversion
    k_cvt_w<<<(2 * D_IN * D_H + 255) / 256, 256>>>(W1, Wmu, Wls);

    // layer 1: tensor-core transform (pre-scaled table)
    k_gemm1<<<N_PAD / 64, 256>>>(x);

    // aggregations (warp per node)
    {
        long long total = (long long)N_NODES * 32;
        int blocks = (int)((total + 255) / 256);
        k_agg<1><<<blocks, 256>>>(b1);
        k_agg<2><<<blocks, 256>>>(nullptr);
    }

    // output tensor-core GEMM + reparameterization
    k_gemm2<<<N_PAD / 64, 256>>>(bmu, bls, eps, out);
}